// round 5
// baseline (speedup 1.0000x reference)
#include <cuda_runtime.h>

// SegmentPhysicsModel — 3 sign-selected single-diode solves per sample.
//
// R5 changes vs R4 (ncu 5.54us):
//  * No shared-memory staging. Each thread loads its 8 used features directly
//    (features 8-10 — year/month/day — never enter the math). A warp's 32
//    samples span the same 11 cache lines either way; this removes
//    STS + syncwarp + LDS (~60 cyc) from the critical path and front-batches
//    8 independent LDGs (MLP_p1 = 8).
//  * All three full-precision divides replaced by raw MUFU.RCP (1 instr vs
//    ~8-instr div sequence, and they head the dependent compute chain).
//    1-ulp rcp error -> ~1e-8 relative on the output. 
//  * NITER 3 -> 2 (contraction <= 3e-4/step on <=5e-3 A initial error:
//    2 steps land ~5e-10 A from the fixed point).

#define TPB        256
#define NFEAT      11

#define JSC        170.0
#define ALPHA_ISC  0.0006f
#define T_REFC     298.15f
#define RS         0.01f
#define INV_RSH    0.002f
#define INV_GREF   (1.0f/1366.0f)
#define SOLAR_C    1366.0f
#define SUN_DIST   149600000.0f
#define NKB        (2.5f * 8.617333262e-05f)
#define LOG2E      1.4426950408889634

#define VT_REF_D   (2.5 * 8.617333262e-05 * 298.15)
#define INV_EM1_ARG ((float)(-(2.35 / VT_REF_D) * LOG2E))

#define C_A1       ((float)(JSC * 0.0604 * 0.0398))
#define C_A2       ((float)(JSC * 0.0403 * 0.0306))

#define STEP       0.99984f
#define NITER      2

__device__ __forceinline__ float ex2f(float z) {
    float r;
    asm("ex2.approx.f32 %0, %1;" : "=f"(r) : "f"(z));
    return r;
}

__device__ __forceinline__ float rcpf(float a) {
    float r;
    asm("rcp.approx.f32 %0, %1;" : "=f"(r) : "f"(a));
    return r;
}

__device__ __forceinline__ void fp_step(float& I, float v_cell, float c0,
                                        float i0, float k) {
    float u = fmaf(I, RS, v_cell);
    float e = ex2f(u * k);
    float t = fmaf(-i0, e, c0);
    t = fmaf(-INV_RSH, u, t);
    I = fmaf(STEP, t - I, I);
}

__global__ void __launch_bounds__(TPB)
segment_physics_kernel(const float* __restrict__ x,
                       const float* __restrict__ f_xn,
                       const float* __restrict__ f_yn,
                       const float* __restrict__ f_xp,
                       const float* __restrict__ f_yp,
                       float* __restrict__ out, int n) {
    int i = blockIdx.x * TPB + threadIdx.x;
    if (i >= n) return;

    // Scalar broadcast factors — issue first, overlap with x loads.
    float v_xn = f_xn[0], v_yn = f_yn[0], v_xp = f_xp[0], v_yp = f_yp[0];

    const float* p = x + (size_t)i * NFEAT;
    float sx   = __ldg(p + 0);
    float sy   = __ldg(p + 1);
    float tpx  = __ldg(p + 2);
    float tnx  = __ldg(p + 3);
    float tpy  = __ldg(p + 4);
    float tny  = __ldg(p + 5);
    float V    = __ldg(p + 6);
    float dist = __ldg(p + 7);

    float irr;
    {
        float r = SUN_DIST * rcpf(dist);
        irr = SOLAR_C * r * r;
    }

    // Dark-side panel's root is negative -> clamps to 0; keep only lit side.
    bool  xp = sx > 0.0f;
    float Gx = irr * fabsf(sx);
    float Tx = xp ? tpx : tnx;
    float fx = xp ? v_xp : v_xn;

    bool  yp = sy > 0.0f;
    float Gy = irr * fabsf(sy);
    float Ty = yp ? tpy : tny;
    float fy = yp ? v_yp : v_yn;
    float cAY  = yp ? C_A2 : C_A1;     // y_pos: small cells, y_neg: large
    float parY = yp ? 10.0f : 6.0f;    // 180/18 vs 108/18

    float v_cell  = V * (1.0f / 18.0f);
    float inv_em1 = ex2f(INV_EM1_ARG);

    float gtx = (Gx * INV_GREF) * fmaf(ALPHA_ISC, Tx - T_REFC, 1.0f);
    float gty = (Gy * INV_GREF) * fmaf(ALPHA_ISC, Ty - T_REFC, 1.0f);

    float kx = (float)LOG2E * rcpf(NKB * Tx);
    float ky = (float)LOG2E * rcpf(NKB * Ty);

    float iph1 = C_A1 * gtx;           // X large cells  (parallel = 2)
    float iph2 = C_A2 * gtx;           // X small cells  (parallel = 7)
    float iph3 = cAY  * gty;           // Y selected config

    float i0_1 = C_A1 * inv_em1;
    float i0_2 = C_A2 * inv_em1;
    float i0_3 = cAY  * inv_em1;

    float c0_1 = iph1 + i0_1;
    float c0_2 = iph2 + i0_2;
    float c0_3 = iph3 + i0_3;

    float I1 = iph1, I2 = iph2, I3 = iph3;

    #pragma unroll
    for (int it = 0; it < NITER; ++it) {
        fp_step(I1, v_cell, c0_1, i0_1, kx);
        fp_step(I2, v_cell, c0_2, i0_2, kx);
        fp_step(I3, v_cell, c0_3, i0_3, ky);
    }

    float ix = fx * fmaf(2.0f, fmaxf(I1, 0.0f), 7.0f * fmaxf(I2, 0.0f));
    float iy = fy * parY * fmaxf(I3, 0.0f);
    out[i] = 0.92f * (ix + iy);
}

extern "C" void kernel_launch(void* const* d_in, const int* in_sizes, int n_in,
                              void* d_out, int out_size) {
    const float* x    = (const float*)d_in[0];
    const float* f_xn = (const float*)d_in[1];
    const float* f_yn = (const float*)d_in[2];
    const float* f_xp = (const float*)d_in[3];
    const float* f_yp = (const float*)d_in[4];
    float* out = (float*)d_out;

    int n = in_sizes[0] / NFEAT;
    int blocks = (n + TPB - 1) / TPB;
    segment_physics_kernel<<<blocks, TPB>>>(x, f_xn, f_yn, f_xp, f_yp, out, n);
}